// round 6
// baseline (speedup 1.0000x reference)
#include <cuda_runtime.h>
#include <cuda_fp16.h>

#define W_   128
#define H_   256
#define D_   256
#define NVOX 16777216         // 2*256*256*128
#define NVEC 4194304          // NVOX/4
#define SD_  32768            // stride along D = H_*W_
#define LAMB 0.01f
#define FULLM 0xffffffffu

// Persistent scratch: z fields stored in fp16 (32 MB each).
__device__ __half g_z0[NVOX];
__device__ __half g_z1[NVOX];
__device__ __half g_z2[NVOX];

__device__ __forceinline__ float4 ld4(const float* p) { return *(const float4*)p; }

// fp16 vec4 load/store (8 bytes), converting to/from fp32.
__device__ __forceinline__ float4 ldh4(const __half* p, int idx) {
    uint2 raw = *(const uint2*)(p + idx);
    __half2 a = *(const __half2*)&raw.x;
    __half2 b = *(const __half2*)&raw.y;
    float2 fa = __half22float2(a);
    float2 fb = __half22float2(b);
    return make_float4(fa.x, fa.y, fb.x, fb.y);
}
__device__ __forceinline__ void sth4(__half* p, int idx, float4 v) {
    __half2 a = __floats2half2_rn(v.x, v.y);
    __half2 b = __floats2half2_rn(v.z, v.w);
    uint2 raw;
    raw.x = *(const unsigned int*)&a;
    raw.y = *(const unsigned int*)&b;
    *(uint2*)(p + idx) = raw;
}

__device__ __forceinline__ float zf(float t, float s) { return t - LAMB * (t - s); }
__device__ __forceinline__ float clip(float x, float sg) { return fminf(fmaxf(x, -sg), sg); }
__device__ __forceinline__ float4 zf4(float4 t, float4 s) {
    float4 z;
    z.x = zf(t.x, s.x); z.y = zf(t.y, s.y);
    z.z = zf(t.z, s.z); z.w = zf(t.w, s.w);
    return z;
}
__device__ __forceinline__ float4 sub4(float4 a, float4 b) {
    float4 r; r.x = a.x-b.x; r.y = a.y-b.y; r.z = a.z-b.z; r.w = a.w-b.w; return r;
}
// one dual stage: pn = clip(p - dz, sg); return pn + nt*(pn - p)
__device__ __forceinline__ float dualu(float p, float dz, float sg, float nt) {
    float pn = clip(p - dz, sg);
    return pn + nt * (pn - p);
}
__device__ __forceinline__ float4 dualu4(float4 p, float4 dz, float sg, float nt) {
    float4 r;
    r.x = dualu(p.x, dz.x, sg, nt);
    r.y = dualu(p.y, dz.y, sg, nt);
    r.z = dualu(p.z, dz.z, sg, nt);
    r.w = dualu(p.w, dz.w, sg, nt);
    return r;
}
// chain the dual through NS cascades starting from 0
template <int NS>
__device__ __forceinline__ float4 chain4(const float4* dz, float sg, const float* nt) {
    float4 p = make_float4(0.f, 0.f, 0.f, 0.f);
#pragma unroll
    for (int c = 0; c < NS; c++) p = dualu4(p, dz[c], sg, nt[c]);
    return p;
}

// ---------------- cascade 0 ----------------
// z0 computed from image,sino; 1-stage duals; writes out0, t1, z0, z1 (fp16).
__global__ __launch_bounds__(256)
void dtv_c0(const float* __restrict__ image, const float* __restrict__ sino,
            const float* __restrict__ sig, const float* __restrict__ ntp,
            __half* __restrict__ wz0, __half* __restrict__ wz1,
            float* __restrict__ tout, float* __restrict__ out0)
{
    int v = blockIdx.x * 256 + threadIdx.x;
    int idx = v << 2;
    int lane = threadIdx.x & 31;
    int h = (idx >> 7) & (H_ - 1);
    int d = (idx >> 15) & (D_ - 1);
    bool dhi = (d < D_ - 1), dlo = (d > 0);
    bool hhi = (h < H_ - 1), hlo = (h > 0);

    float4 t4 = ld4(image + idx);
    float4 s4 = ld4(sino + idx);
    float4 z  = zf4(t4, s4);

    float4 zdp = dhi ? zf4(ld4(image + idx + SD_), ld4(sino + idx + SD_)) : z;
    float4 zdm = dlo ? zf4(ld4(image + idx - SD_), ld4(sino + idx - SD_)) : z;
    float4 zhp = hhi ? zf4(ld4(image + idx + W_),  ld4(sino + idx + W_))  : z;
    float4 zhm = hlo ? zf4(ld4(image + idx - W_),  ld4(sino + idx - W_))  : z;
    float zp4 = __shfl_down_sync(FULLM, z.x, 1);
    if (lane == 31) zp4 = z.w;

    float sg0 = __ldg(sig+0), sg1 = __ldg(sig+1), sg2 = __ldg(sig+2), sg3 = __ldg(sig+3);
    float nt0 = __ldg(ntp + 0);

    // D axis
    float4 pe  = dualu4(make_float4(0,0,0,0), sub4(zdp, z), sg0, nt0);
    float4 pem = dualu4(make_float4(0,0,0,0), sub4(z, zdm), sg0, nt0);
    // H axis
    float4 qe  = dualu4(make_float4(0,0,0,0), sub4(zhp, z), sg1, nt0);
    float4 qem = dualu4(make_float4(0,0,0,0), sub4(z, zhm), sg1, nt0);
    // W axis
    float4 dzw;
    dzw.x = z.y - z.x; dzw.y = z.z - z.y; dzw.z = z.w - z.z; dzw.w = zp4 - z.w;
    float4 se = dualu4(make_float4(0,0,0,0), dzw, sg2, nt0);
    float sem = __shfl_up_sync(FULLM, se.w, 1);

    float4 o;
    o.x = (dlo ? pem.x : 0.f) - pe.x + (hlo ? qem.x : 0.f) - qe.x
        + ((lane > 0) ? sem : 0.f) - se.x + clip(z.x, sg3);
    o.y = (dlo ? pem.y : 0.f) - pe.y + (hlo ? qem.y : 0.f) - qe.y
        + se.x - se.y + clip(z.y, sg3);
    o.z = (dlo ? pem.z : 0.f) - pe.z + (hlo ? qem.z : 0.f) - qe.z
        + se.y - se.z + clip(z.z, sg3);
    o.w = (dlo ? pem.w : 0.f) - pe.w + (hlo ? qem.w : 0.f) - qe.w
        + se.z - se.w + clip(z.w, sg3);

    *(float4*)(tout + idx) = o;
    *(float4*)(out0 + idx) = t4;
    sth4(wz0, idx, z);
    sth4(wz1, idx, zf4(o, s4));
}

// ---------------- cascades 1 & 2 ----------------
// NS = number of z fields (2 for c1, 3 for c2); z fields are fp16.
template <int NS, bool LAST>
__global__ __launch_bounds__(256)
void dtv_chain(const __half* __restrict__ za, const __half* __restrict__ zb,
               const __half* __restrict__ zc, const float* __restrict__ sino,
               const float* __restrict__ sig, const float* __restrict__ ntp,
               __half* __restrict__ wz, float* __restrict__ tout)
{
    int v = blockIdx.x * 256 + threadIdx.x;
    int idx = v << 2;
    int lane = threadIdx.x & 31;
    int h = (idx >> 7) & (H_ - 1);
    int d = (idx >> 15) & (D_ - 1);
    bool dhi = (d < D_ - 1), dlo = (d > 0);
    bool hhi = (h < H_ - 1), hlo = (h > 0);

    const __half* zs[3] = { za, zb, zc };

    float sg0 = __ldg(sig+0), sg1 = __ldg(sig+1), sg2 = __ldg(sig+2), sg3 = __ldg(sig+3);
    float nt[3];
#pragma unroll
    for (int c = 0; c < NS; c++) nt[c] = __ldg(ntp + c);

    float4 z[NS];
#pragma unroll
    for (int c = 0; c < NS; c++) z[c] = ldh4(zs[c], idx);

    float4 o = make_float4(0.f, 0.f, 0.f, 0.f);

    // ---- D axis ----
    {
        float4 dzx[NS], dzm[NS];
#pragma unroll
        for (int c = 0; c < NS; c++) {
            float4 zdp = dhi ? ldh4(zs[c], idx + SD_) : z[c];
            float4 zdm = dlo ? ldh4(zs[c], idx - SD_) : z[c];
            dzx[c] = sub4(zdp, z[c]);
            dzm[c] = sub4(z[c], zdm);
        }
        float4 pe  = chain4<NS>(dzx, sg0, nt);
        float4 pem = chain4<NS>(dzm, sg0, nt);
        float lm = dlo ? 1.f : 0.f;
        o.x += lm * pem.x - pe.x;
        o.y += lm * pem.y - pe.y;
        o.z += lm * pem.z - pe.z;
        o.w += lm * pem.w - pe.w;
    }
    // ---- H axis ----
    {
        float4 dzx[NS], dzm[NS];
#pragma unroll
        for (int c = 0; c < NS; c++) {
            float4 zhp = hhi ? ldh4(zs[c], idx + W_) : z[c];
            float4 zhm = hlo ? ldh4(zs[c], idx - W_) : z[c];
            dzx[c] = sub4(zhp, z[c]);
            dzm[c] = sub4(z[c], zhm);
        }
        float4 qe  = chain4<NS>(dzx, sg1, nt);
        float4 qem = chain4<NS>(dzm, sg1, nt);
        float lm = hlo ? 1.f : 0.f;
        o.x += lm * qem.x - qe.x;
        o.y += lm * qem.y - qe.y;
        o.z += lm * qem.z - qe.z;
        o.w += lm * qem.w - qe.w;
    }
    // ---- W axis ----
    {
        float4 dzw[NS];
#pragma unroll
        for (int c = 0; c < NS; c++) {
            float zp4 = __shfl_down_sync(FULLM, z[c].x, 1);
            if (lane == 31) zp4 = z[c].w;
            dzw[c].x = z[c].y - z[c].x;
            dzw[c].y = z[c].z - z[c].y;
            dzw[c].z = z[c].w - z[c].z;
            dzw[c].w = zp4 - z[c].w;
        }
        float4 se = chain4<NS>(dzw, sg2, nt);
        float sem = __shfl_up_sync(FULLM, se.w, 1);
        o.x += ((lane > 0) ? sem : 0.f) - se.x;
        o.y += se.x - se.y;
        o.z += se.y - se.z;
        o.w += se.z - se.w;   // se.w == 0 at lane31 automatically (dz=0 chain)
    }

    float4 zl = z[NS - 1];
    o.x += clip(zl.x, sg3);
    o.y += clip(zl.y, sg3);
    o.z += clip(zl.z, sg3);
    o.w += clip(zl.w, sg3);

    *(float4*)(tout + idx) = o;
    if (!LAST) {
        float4 s4 = ld4(sino + idx);
        sth4(wz, idx, zf4(o, s4));
    }
}

extern "C" void kernel_launch(void* const* d_in, const int* in_sizes, int n_in,
                              void* d_out, int out_size)
{
    const float* image = nullptr;
    const float* sino  = nullptr;
    const float* sigma = nullptr;
    const float* ntv   = nullptr;
    for (int i = 0; i < n_in; i++) {
        if (in_sizes[i] == 4) sigma = (const float*)d_in[i];
        else if (in_sizes[i] == 3) ntv = (const float*)d_in[i];
        else if (!image) image = (const float*)d_in[i];
        else if (!sino)  sino  = (const float*)d_in[i];
    }
    float* out = (float*)d_out;

    __half *z0a, *z1a, *z2a;
    cudaGetSymbolAddress((void**)&z0a, g_z0);
    cudaGetSymbolAddress((void**)&z1a, g_z1);
    cudaGetSymbolAddress((void**)&z2a, g_z2);

    dim3 grid(NVEC / 256), block(256);

    // cascade 0: writes out0, t1, z0, z1
    dtv_c0<<<grid, block>>>(image, sino, sigma, ntv,
                            z0a, z1a, out + 1u * NVOX, out);
    // cascade 1: reads z0,z1; writes t2, z2
    dtv_chain<2, false><<<grid, block>>>(z0a, z1a, nullptr, sino, sigma, ntv,
                                         z2a, out + 2u * NVOX);
    // cascade 2: reads z0,z1,z2; writes t3
    dtv_chain<3, true ><<<grid, block>>>(z0a, z1a, z2a, nullptr, sigma, ntv,
                                         nullptr, out + 3u * NVOX);
}